// round 10
// baseline (speedup 1.0000x reference)
#include <cuda_runtime.h>
#include <cstdint>

#define BATCH 8
#define TLEN 4096
#define INDIM 128
#define OUTDIM 128
#define HID 256
#define PITCH 136              // floats per t-data smem row
#define KC 32                  // K-chunk
#define BBUF (KC * PITCH)      // t-data floats per stage (4352)
#define WBUF 4096              // weight-fragment floats per stage
#define NSTAGE 3
#define SMEM_BYTES (NSTAGE * (BBUF + WBUF) * 4)   // 101376

// ---- scratch (device globals: allocation-free rule) ----
__device__ float g_lam_re[HID];
__device__ float g_lam_im[HID];
__device__ float g_mag[HID];
__device__ float g_th[HID];
__device__ float g_bx_re[(size_t)BATCH * HID * TLEN];    // [b][h][t]
__device__ float g_bx_im[(size_t)BATCH * HID * TLEN];
__device__ float g_xt[(size_t)BATCH * INDIM * TLEN];     // [b][i][t] (tf32-rounded)
// weight fragments, mma m16n8k8 order: [K8][mt][lane][4]
__device__ float g_wf1[16 * 32 * 32 * 4];                // gemm1: M=512 (g*Bre | g*Bim), K=128
__device__ float g_wf2[80 * 8 * 32 * 4];                 // gemm2: M=128 (o), K=640 (Cre|-Cim|D)

// ---- helpers ----
__device__ __forceinline__ float to_tf32(float x) {
    unsigned u;
    asm("cvt.rna.tf32.f32 %0, %1;" : "=r"(u) : "f"(x));
    return __uint_as_float(u);
}
__device__ __forceinline__ void mma8(float& d0, float& d1, float& d2, float& d3,
                                     float a0, float a1, float a2, float a3,
                                     float b0, float b1) {
    asm("mma.sync.aligned.m16n8k8.row.col.f32.tf32.tf32.f32 "
        "{%0,%1,%2,%3}, {%4,%5,%6,%7}, {%8,%9}, {%0,%1,%2,%3};"
        : "+f"(d0), "+f"(d1), "+f"(d2), "+f"(d3)
        : "r"(__float_as_uint(a0)), "r"(__float_as_uint(a1)),
          "r"(__float_as_uint(a2)), "r"(__float_as_uint(a3)),
          "r"(__float_as_uint(b0)), "r"(__float_as_uint(b1)));
}
__device__ __forceinline__ unsigned smem_u32(const void* p) {
    return (unsigned)__cvta_generic_to_shared(p);
}
__device__ __forceinline__ void cp16(unsigned s, const void* g) {
    asm volatile("cp.async.cg.shared.global [%0], [%1], 16;" :: "r"(s), "l"(g));
}
__device__ __forceinline__ void cp_commit() { asm volatile("cp.async.commit_group;"); }
__device__ __forceinline__ void cp_wait1()  { asm volatile("cp.async.wait_group 1;"); }
__device__ __forceinline__ void cp_wait0()  { asm volatile("cp.async.wait_group 0;"); }

// ---------------------------------------------------------------------------
// prep_all: fused prep_xt (transpose) + prep_w (fragments) + params
// ---------------------------------------------------------------------------
#define WF1_N (16 * 32 * 32 * 4)   // 262144 floats
#define WF2_N (80 * 8 * 32 * 4)    // 81920 floats
#define NB_XT 4096
#define NB_W  ((WF1_N + WF2_N) / 256)   // 1344
#define NB_ALL (NB_XT + NB_W + 1)

__global__ __launch_bounds__(256)
void prep_all_kernel(const float* __restrict__ X,
                     const float* __restrict__ nu_log,
                     const float* __restrict__ theta_log,
                     const float* __restrict__ Bre, const float* __restrict__ Bim,
                     const float* __restrict__ Cre, const float* __restrict__ Cim,
                     const float* __restrict__ Dm) {
    __shared__ float tile[32][33];
    int bid = blockIdx.x;
    int tid = threadIdx.x;

    if (bid < NB_XT) {
        int t0 = (bid & 127) * 32;
        int i0 = ((bid >> 7) & 3) * 32;
        int b  = bid >> 9;
#pragma unroll
        for (int r = 0; r < 4; r++) {
            int idx = tid + 256 * r;
            int tl = idx >> 5, il = idx & 31;
            tile[tl][il] = X[((size_t)b * TLEN + t0 + tl) * INDIM + i0 + il];
        }
        __syncthreads();
#pragma unroll
        for (int r = 0; r < 4; r++) {
            int idx = tid + 256 * r;
            int il = idx >> 5, tl = idx & 31;
            g_xt[((size_t)b * INDIM + i0 + il) * TLEN + t0 + tl] = to_tf32(tile[tl][il]);
        }
    } else if (bid < NB_XT + NB_W) {
        int idx = (bid - NB_XT) * 256 + tid;
        if (idx < WF1_N) {
            int j = idx & 3, lane = (idx >> 2) & 31, mt = (idx >> 7) & 31, K8 = idx >> 12;
            int g = lane >> 2, tig = lane & 3;
            int m = mt * 16 + g + (j & 1) * 8;
            int i = K8 * 8 + tig + (j >> 1) * 4;
            int h = m & 255;
            float mag = expf(-expf(nu_log[h]));
            float gam = sqrtf(fmaxf(1.0f - mag * mag, 0.0f));
            float v = (m < 256) ? gam * Bre[(size_t)h * INDIM + i]
                                : gam * Bim[(size_t)h * INDIM + i];
            g_wf1[idx] = to_tf32(v);
        } else {
            int e = idx - WF1_N;
            int j = e & 3, lane = (e >> 2) & 31, mt = (e >> 7) & 7, K8 = e >> 10;
            int g = lane >> 2, tig = lane & 3;
            int o = mt * 16 + g + (j & 1) * 8;
            int k = K8 * 8 + tig + (j >> 1) * 4;
            float v;
            if (k < 256)      v =  Cre[(size_t)o * HID + k];
            else if (k < 512) v = -Cim[(size_t)o * HID + (k - 256)];
            else              v =  Dm[(size_t)o * INDIM + (k - 512)];
            g_wf2[e] = to_tf32(v);
        }
    } else {
        int h = tid;
        if (h < HID) {
            float mag = expf(-expf(nu_log[h]));
            float th  = expf(theta_log[h]);
            g_mag[h] = mag;
            g_th[h]  = th;
            g_lam_re[h] = mag * cosf(th);
            g_lam_im[h] = mag * sinf(th);
        }
    }
}

// ---------------------------------------------------------------------------
// smem fill helpers
// ---------------------------------------------------------------------------
__device__ __forceinline__ void fill_b(float* Bs, int buf, const float* arow,
                                       int row, int cq) {
    unsigned sb = smem_u32(&Bs[buf * BBUF + row * PITCH]);
#pragma unroll
    for (int r = 0; r < 4; r++) {
        int c = cq + 8 * r;
        cp16(sb + 16 * c, arow + 4 * c);
    }
}
__device__ __forceinline__ void fill_w(float* Wf, int buf, const float4* wsrc,
                                       int k8stride, int tid) {
    unsigned sw = smem_u32(&Wf[buf * WBUF]);
#pragma unroll
    for (int r = 0; r < 4; r++) {
        int fidx = tid + r * 256;
        int k8l = fidx >> 8, rem = fidx & 255;
        cp16(sw + 16 * fidx, wsrc + k8l * k8stride + rem);
    }
}
// compute one KC=32 chunk: A = weight frags (LDS.128), B = t rows
__device__ __forceinline__ void compute_chunk(const float* Bs, const float* Wf,
                                              int buf, int warp_m, int warp_n,
                                              int lane, int g, int tig,
                                              float acc[4][4][4]) {
    const float4* Wf4 = (const float4*)&Wf[buf * WBUF];
    const float*  Bsb = &Bs[buf * BBUF];
#pragma unroll
    for (int ks = 0; ks < 4; ks++) {
        float4 a[4];
#pragma unroll
        for (int mi = 0; mi < 4; mi++)
            a[mi] = Wf4[(ks * 8 + warp_m * 4 + mi) * 32 + lane];
        float b0[4], b1[4];
#pragma unroll
        for (int ni = 0; ni < 4; ni++) {
            int tw = warp_n * 32 + ni * 8 + g;
            b0[ni] = Bsb[(ks * 8 + tig) * PITCH + tw];
            b1[ni] = Bsb[(ks * 8 + tig + 4) * PITCH + tw];
        }
#pragma unroll
        for (int mi = 0; mi < 4; mi++)
#pragma unroll
            for (int ni = 0; ni < 4; ni++)
                mma8(acc[mi][ni][0], acc[mi][ni][1], acc[mi][ni][2], acc[mi][ni][3],
                     a[mi].x, a[mi].y, a[mi].z, a[mi].w, b0[ni], b1[ni]);
    }
}

// ---------------------------------------------------------------------------
// GEMM1: out[m 512][t] = W[m][k] * Xt[k][t]
// Grid (32 t, 4 mblk, 8 b) = 1024 CTAs. 3-stage cp.async, 1 sync/chunk.
// ---------------------------------------------------------------------------
__global__ __launch_bounds__(256)
void gemm1_kernel() {
    extern __shared__ float smem[];
    float* Bs = smem;
    float* Wf = smem + NSTAGE * BBUF;

    int tid = threadIdx.x, lane = tid & 31, wid = tid >> 5;
    int warp_m = wid >> 2, warp_n = wid & 3;
    int g = lane >> 2, tig = lane & 3;
    int b = blockIdx.z, t0 = blockIdx.x * 128;
    int mt0 = blockIdx.y * 8;
    int m0 = blockIdx.y * 128;

    const int row = tid >> 3, cq = tid & 7;
    const int NCH = INDIM / KC;   // 4
    const float4* wbase = (const float4*)g_wf1;

    auto fill1 = [&](int c) {
        const float* arow = g_xt + ((size_t)b * INDIM + c * KC + row) * TLEN + t0;
        fill_b(Bs, c % NSTAGE, arow, row, cq);
        fill_w(Wf, c % NSTAGE, wbase + (size_t)((c * 4) * 32 + mt0) * 32, 32 * 32, tid);
        cp_commit();
    };

    fill1(0);
    fill1(1);

    float acc[4][4][4];
#pragma unroll
    for (int mi = 0; mi < 4; mi++)
#pragma unroll
        for (int ni = 0; ni < 4; ni++)
#pragma unroll
            for (int q = 0; q < 4; q++) acc[mi][ni][q] = 0.f;

    for (int c = 0; c < NCH; c++) {
        if (c + 2 < NCH) cp_wait1(); else cp_wait0();
        __syncthreads();
        if (c + 2 < NCH) fill1(c + 2);
        compute_chunk(Bs, Wf, c % NSTAGE, warp_m, warp_n, lane, g, tig, acc);
    }

    float* dst = (m0 < 256) ? g_bx_re : g_bx_im;
    int hbase = m0 & 255;
#pragma unroll
    for (int mi = 0; mi < 4; mi++) {
        int h = hbase + warp_m * 64 + mi * 16 + g;
#pragma unroll
        for (int ni = 0; ni < 4; ni++) {
            int t = t0 + warp_n * 32 + ni * 8 + 2 * tig;
            *(float2*)&dst[((size_t)b * HID + h) * TLEN + t] =
                make_float2(acc[mi][ni][0], acc[mi][ni][1]);
            *(float2*)&dst[((size_t)b * HID + h + 8) * TLEN + t] =
                make_float2(acc[mi][ni][2], acc[mi][ni][3]);
        }
    }
}

// ---------------------------------------------------------------------------
// Scan: inclusive complex scan over t, 8 elems/lane, PREFETCH DISTANCE 2
// (8 float4 in flight per warp -> ~2x streaming BW), in place on g_bx.
// ---------------------------------------------------------------------------
__global__ __launch_bounds__(256)
void scan_kernel() {
    int wg   = (blockIdx.x * blockDim.x + threadIdx.x) >> 5;
    int lane = threadIdx.x & 31;
    if (wg >= BATCH * HID) return;
    int b = wg >> 8;
    int h = wg & (HID - 1);

    float lr[8], li[8];
    lr[0] = g_lam_re[h]; li[0] = g_lam_im[h];
#pragma unroll
    for (int k = 1; k < 8; k++) {
        lr[k] = lr[k-1] * lr[0] - li[k-1] * li[0];
        li[k] = lr[k-1] * li[0] + li[k-1] * lr[0];
    }
    float pdr[5], pdi[5];
    pdr[0] = lr[7]; pdi[0] = li[7];
#pragma unroll
    for (int s = 1; s < 5; s++) {
        pdr[s] = pdr[s-1] * pdr[s-1] - pdi[s-1] * pdi[s-1];
        pdi[s] = 2.f * pdr[s-1] * pdi[s-1];
    }
    float mag = g_mag[h], th = g_th[h];
    float mp  = powf(mag, 8.f * (float)lane);
    float sa, ca;
    sincosf(th * 8.f * (float)lane, &sa, &ca);
    float c8r = mp * ca, c8i = mp * sa;

    float ccr = 0.f, cci = 0.f;
    size_t base = ((size_t)b * HID + h) * TLEN;
    const int NCH = TLEN / 256;   // 16

    size_t off0 = base + (size_t)lane * 8;

    // prefetch queue, depth 2
    float4 br0[2], br1[2], bi0[2], bi1[2];
#pragma unroll
    for (int p = 0; p < 2; p++) {
        size_t o = off0 + (size_t)p * 256;
        br0[p] = *(const float4*)&g_bx_re[o];
        br1[p] = *(const float4*)&g_bx_re[o + 4];
        bi0[p] = *(const float4*)&g_bx_im[o];
        bi1[p] = *(const float4*)&g_bx_im[o + 4];
    }

    for (int c = 0; c < NCH; c++) {
        int q = c & 1;
        float xr[8] = {br0[q].x, br0[q].y, br0[q].z, br0[q].w,
                       br1[q].x, br1[q].y, br1[q].z, br1[q].w};
        float xi[8] = {bi0[q].x, bi0[q].y, bi0[q].z, bi0[q].w,
                       bi1[q].x, bi1[q].y, bi1[q].z, bi1[q].w};
        size_t coff = off0 + (size_t)c * 256;
        if (c + 2 < NCH) {
            size_t o = off0 + (size_t)(c + 2) * 256;
            br0[q] = *(const float4*)&g_bx_re[o];
            br1[q] = *(const float4*)&g_bx_re[o + 4];
            bi0[q] = *(const float4*)&g_bx_im[o];
            bi1[q] = *(const float4*)&g_bx_im[o + 4];
        }

        float yr[8], yi[8];
        yr[0] = xr[0]; yi[0] = xi[0];
#pragma unroll
        for (int k = 1; k < 8; k++) {
            yr[k] = xr[k] + lr[0] * yr[k-1] - li[0] * yi[k-1];
            yi[k] = xi[k] + lr[0] * yi[k-1] + li[0] * yr[k-1];
        }

        float sr = yr[7], si = yi[7];
#pragma unroll
        for (int s = 0; s < 5; s++) {
            int d = 1 << s;
            float tr = __shfl_up_sync(0xffffffffu, sr, d);
            float ti = __shfl_up_sync(0xffffffffu, si, d);
            if (lane >= d) {
                sr += pdr[s] * tr - pdi[s] * ti;
                si += pdr[s] * ti + pdi[s] * tr;
            }
        }
        float qr = __shfl_up_sync(0xffffffffu, sr, 1);
        float qi = __shfl_up_sync(0xffffffffu, si, 1);
        if (lane == 0) { qr = 0.f; qi = 0.f; }
        qr += c8r * ccr - c8i * cci;
        qi += c8r * cci + c8i * ccr;

        float or_[8], oi_[8];
#pragma unroll
        for (int k = 0; k < 8; k++) {
            or_[k] = yr[k] + lr[k] * qr - li[k] * qi;
            oi_[k] = yi[k] + lr[k] * qi + li[k] * qr;
        }

        ccr = __shfl_sync(0xffffffffu, or_[7], 31);
        cci = __shfl_sync(0xffffffffu, oi_[7], 31);

        *(float4*)&g_bx_re[coff]     = make_float4(to_tf32(or_[0]), to_tf32(or_[1]), to_tf32(or_[2]), to_tf32(or_[3]));
        *(float4*)&g_bx_re[coff + 4] = make_float4(to_tf32(or_[4]), to_tf32(or_[5]), to_tf32(or_[6]), to_tf32(or_[7]));
        *(float4*)&g_bx_im[coff]     = make_float4(to_tf32(oi_[0]), to_tf32(oi_[1]), to_tf32(oi_[2]), to_tf32(oi_[3]));
        *(float4*)&g_bx_im[coff + 4] = make_float4(to_tf32(oi_[4]), to_tf32(oi_[5]), to_tf32(oi_[6]), to_tf32(oi_[7]));
    }
}

// ---------------------------------------------------------------------------
// GEMM2: Y[t][o] = sum_{k<640} Wt2[o][k] * A[k][t]
// 3-stage cp.async, single __syncthreads per chunk. Grid (32, 8).
// ---------------------------------------------------------------------------
__global__ __launch_bounds__(256)
void gemm2_kernel(float* __restrict__ Y) {
    extern __shared__ float smemf[];
    float* Bs = smemf;
    float* Wf = smemf + NSTAGE * BBUF;

    int tid = threadIdx.x, lane = tid & 31, wid = tid >> 5;
    int warp_m = wid >> 2, warp_n = wid & 3;
    int g = lane >> 2, tig = lane & 3;
    int b = blockIdx.y, t0 = blockIdx.x * 128;

    float acc[4][4][4];
#pragma unroll
    for (int mi = 0; mi < 4; mi++)
#pragma unroll
        for (int ni = 0; ni < 4; ni++)
#pragma unroll
            for (int q = 0; q < 4; q++) acc[mi][ni][q] = 0.f;

    const int row = tid >> 3, cq = tid & 7;
    const int NCH = 640 / KC;   // 20
    const float4* wbase = (const float4*)g_wf2;

    auto arow_of = [&](int k) -> const float* {
        if (k < 256)      return g_bx_re + ((size_t)b * HID + k) * TLEN + t0;
        else if (k < 512) return g_bx_im + ((size_t)b * HID + (k - 256)) * TLEN + t0;
        else              return g_xt   + ((size_t)b * INDIM + (k - 512)) * TLEN + t0;
    };
    auto fill2 = [&](int c) {
        fill_b(Bs, c % NSTAGE, arow_of(c * KC + row), row, cq);
        fill_w(Wf, c % NSTAGE, wbase + (size_t)(c * 4) * 256, 8 * 32, tid);
        cp_commit();
    };

    fill2(0);
    fill2(1);

    for (int c = 0; c < NCH; c++) {
        if (c + 2 < NCH) cp_wait1(); else cp_wait0();
        __syncthreads();
        if (c + 2 < NCH) fill2(c + 2);
        compute_chunk(Bs, Wf, c % NSTAGE, warp_m, warp_n, lane, g, tig, acc);
    }

#pragma unroll
    for (int mi = 0; mi < 4; mi++) {
        int o = warp_m * 64 + mi * 16 + g;
#pragma unroll
        for (int ni = 0; ni < 4; ni++) {
            int t = t0 + warp_n * 32 + ni * 8 + 2 * tig;
            size_t y0 = ((size_t)b * TLEN + t) * OUTDIM;
            size_t y1 = ((size_t)b * TLEN + t + 1) * OUTDIM;
            Y[y0 + o]     = acc[mi][ni][0];
            Y[y1 + o]     = acc[mi][ni][1];
            Y[y0 + o + 8] = acc[mi][ni][2];
            Y[y1 + o + 8] = acc[mi][ni][3];
        }
    }
}

// ---------------------------------------------------------------------------
extern "C" void kernel_launch(void* const* d_in, const int* in_sizes, int n_in,
                              void* d_out, int out_size) {
    const float* X         = (const float*)d_in[0];
    const float* nu_log    = (const float*)d_in[1];
    const float* theta_log = (const float*)d_in[2];
    const float* B_re      = (const float*)d_in[3];
    const float* B_im      = (const float*)d_in[4];
    const float* C_re      = (const float*)d_in[5];
    const float* C_im      = (const float*)d_in[6];
    const float* D         = (const float*)d_in[7];
    float* Y = (float*)d_out;

    cudaFuncSetAttribute(gemm1_kernel, cudaFuncAttributeMaxDynamicSharedMemorySize, SMEM_BYTES);
    cudaFuncSetAttribute(gemm2_kernel, cudaFuncAttributeMaxDynamicSharedMemorySize, SMEM_BYTES);

    prep_all_kernel<<<NB_ALL, 256>>>(X, nu_log, theta_log, B_re, B_im, C_re, C_im, D);

    dim3 g1(TLEN / 128, 4, BATCH);
    gemm1_kernel<<<g1, 256, SMEM_BYTES>>>();

    scan_kernel<<<(BATCH * HID * 32) / 256, 256>>>();

    dim3 g2(TLEN / 128, BATCH);
    gemm2_kernel<<<g2, 256, SMEM_BYTES>>>(Y);
}

// round 11
// speedup vs baseline: 1.2693x; 1.2693x over previous
#include <cuda_runtime.h>
#include <cstdint>

#define BATCH 8
#define TLEN 4096
#define INDIM 128
#define OUTDIM 128
#define HID 256
#define PITCH 132              // fp32 words per t-data smem row (132 mod 32 = 4)
#define KC 32                  // K-chunk (fp32 rows) = 2 k16 mma steps
#define BBUF (KC * PITCH)      // t-data floats per stage (4224)
#define WFRAG 2048             // fp16 frag words (uint32) per stage
#define NSTAGE 3
#define SMEM_BYTES (NSTAGE * (BBUF + WFRAG) * 4)   // 75264

// ---- scratch (device globals: allocation-free rule) ----
__device__ float g_lam_re[HID];
__device__ float g_lam_im[HID];
__device__ float g_mag[HID];
__device__ float g_th[HID];
__device__ float g_bx_re[(size_t)BATCH * HID * TLEN];    // [b][h][t]
__device__ float g_bx_im[(size_t)BATCH * HID * TLEN];
__device__ float g_xt[(size_t)BATCH * INDIM * TLEN];     // [b][i][t]
// fp16 weight fragments, mma m16n8k16 order: [K16][mt][lane][4 words]
__device__ unsigned g_wf1h[8 * 32 * 32 * 4];             // gemm1: M=512, K=128 (32768 words)
__device__ unsigned g_wf2h[40 * 8 * 32 * 4];             // gemm2: M=128, K=640 (40960 words)

// ---- helpers ----
__device__ __forceinline__ unsigned pack_h2(float lo, float hi) {
    unsigned d;
    asm("cvt.rn.f16x2.f32 %0, %1, %2;" : "=r"(d) : "f"(hi), "f"(lo));
    return d;
}
__device__ __forceinline__ void mma16(float& d0, float& d1, float& d2, float& d3,
                                      unsigned a0, unsigned a1, unsigned a2, unsigned a3,
                                      unsigned b0, unsigned b1) {
    asm("mma.sync.aligned.m16n8k16.row.col.f32.f16.f16.f32 "
        "{%0,%1,%2,%3}, {%4,%5,%6,%7}, {%8,%9}, {%0,%1,%2,%3};"
        : "+f"(d0), "+f"(d1), "+f"(d2), "+f"(d3)
        : "r"(a0), "r"(a1), "r"(a2), "r"(a3), "r"(b0), "r"(b1));
}
__device__ __forceinline__ unsigned smem_u32(const void* p) {
    return (unsigned)__cvta_generic_to_shared(p);
}
__device__ __forceinline__ void cp16(unsigned s, const void* g) {
    asm volatile("cp.async.cg.shared.global [%0], [%1], 16;" :: "r"(s), "l"(g));
}
__device__ __forceinline__ void cp_commit() { asm volatile("cp.async.commit_group;"); }
__device__ __forceinline__ void cp_wait1()  { asm volatile("cp.async.wait_group 1;"); }
__device__ __forceinline__ void cp_wait0()  { asm volatile("cp.async.wait_group 0;"); }

// ---------------------------------------------------------------------------
// prep_all: X transpose + fp16 weight fragments + recurrence params
// frag word (K16, mt, lane, j):  g=lane>>2, tig=lane&3
//   m = mt*16 + g + (j&1)*8 ; k0 = K16*16 + 2*tig + (j>>1)*8 ; halves (k0, k0+1)
// ---------------------------------------------------------------------------
#define WF1H_N (8 * 32 * 32 * 4)    // 32768 words
#define WF2H_N (40 * 8 * 32 * 4)    // 40960 words
#define NB_XT 4096
#define NB_W  ((WF1H_N + WF2H_N) / 256)   // 288
#define NB_ALL (NB_XT + NB_W + 1)

__global__ __launch_bounds__(256)
void prep_all_kernel(const float* __restrict__ X,
                     const float* __restrict__ nu_log,
                     const float* __restrict__ theta_log,
                     const float* __restrict__ Bre, const float* __restrict__ Bim,
                     const float* __restrict__ Cre, const float* __restrict__ Cim,
                     const float* __restrict__ Dm) {
    __shared__ float tile[32][33];
    int bid = blockIdx.x;
    int tid = threadIdx.x;

    if (bid < NB_XT) {
        int t0 = (bid & 127) * 32;
        int i0 = ((bid >> 7) & 3) * 32;
        int b  = bid >> 9;
#pragma unroll
        for (int r = 0; r < 4; r++) {
            int idx = tid + 256 * r;
            int tl = idx >> 5, il = idx & 31;
            tile[tl][il] = X[((size_t)b * TLEN + t0 + tl) * INDIM + i0 + il];
        }
        __syncthreads();
#pragma unroll
        for (int r = 0; r < 4; r++) {
            int idx = tid + 256 * r;
            int il = idx >> 5, tl = idx & 31;
            g_xt[((size_t)b * INDIM + i0 + il) * TLEN + t0 + tl] = tile[tl][il];
        }
    } else if (bid < NB_XT + NB_W) {
        int idx = (bid - NB_XT) * 256 + tid;
        if (idx < WF1H_N) {
            int j = idx & 3, lane = (idx >> 2) & 31, mt = (idx >> 7) & 31, K16 = idx >> 12;
            int g = lane >> 2, tig = lane & 3;
            int m = mt * 16 + g + (j & 1) * 8;
            int k0 = K16 * 16 + 2 * tig + (j >> 1) * 8;
            int h = m & 255;
            float mag = expf(-expf(nu_log[h]));
            float gam = sqrtf(fmaxf(1.0f - mag * mag, 0.0f));
            const float* wrow = (m < 256) ? &Bre[(size_t)h * INDIM] : &Bim[(size_t)h * INDIM];
            g_wf1h[idx] = pack_h2(gam * wrow[k0], gam * wrow[k0 + 1]);
        } else {
            int e = idx - WF1H_N;
            int j = e & 3, lane = (e >> 2) & 31, mt = (e >> 7) & 7, K16 = e >> 10;
            int g = lane >> 2, tig = lane & 3;
            int o = mt * 16 + g + (j & 1) * 8;
            int k0 = K16 * 16 + 2 * tig + (j >> 1) * 8;
            float v0, v1;
            if (k0 < 256)      { v0 =  Cre[(size_t)o * HID + k0];         v1 =  Cre[(size_t)o * HID + k0 + 1]; }
            else if (k0 < 512) { v0 = -Cim[(size_t)o * HID + k0 - 256];   v1 = -Cim[(size_t)o * HID + k0 - 255]; }
            else               { v0 =  Dm[(size_t)o * INDIM + k0 - 512];  v1 =  Dm[(size_t)o * INDIM + k0 - 511]; }
            g_wf2h[e] = pack_h2(v0, v1);
        }
    } else {
        int h = tid;
        if (h < HID) {
            float mag = expf(-expf(nu_log[h]));
            float th  = expf(theta_log[h]);
            g_mag[h] = mag;
            g_th[h]  = th;
            g_lam_re[h] = mag * cosf(th);
            g_lam_im[h] = mag * sinf(th);
        }
    }
}

// ---------------------------------------------------------------------------
// smem fill helpers
// ---------------------------------------------------------------------------
__device__ __forceinline__ void fill_b(float* Bs, int buf, const float* arow,
                                       int row, int cq) {
    unsigned sb = smem_u32(&Bs[buf * BBUF + row * PITCH]);
#pragma unroll
    for (int r = 0; r < 4; r++) {
        int c = cq + 8 * r;
        cp16(sb + 16 * c, arow + 4 * c);
    }
}
// copy 512 uint4 of fp16 frags: two 256-uint4 slices at given stride
__device__ __forceinline__ void fill_w(unsigned* Wf, int buf, const uint4* wsrc,
                                       int slice_stride_u4, int tid) {
    unsigned sw = smem_u32(&Wf[buf * WFRAG]);
#pragma unroll
    for (int r = 0; r < 2; r++) {
        int fidx = tid + r * 256;
        int sl = fidx >> 8, rem = fidx & 255;
        cp16(sw + 16 * fidx, wsrc + sl * slice_stride_u4 + rem);
    }
}
// compute one KC=32 chunk = 2 k16 mma-steps.
// A = fp16 weight frags (LDS.128). B = fp32 t rows, packed to f16x2 at consume.
__device__ __forceinline__ void compute_chunk(const float* Bs, const unsigned* Wf,
                                              int buf, int warp_m, int warp_n,
                                              int lane, int g, int tig,
                                              float acc[4][4][4]) {
    const uint4*  Wf4 = (const uint4*)&Wf[buf * WFRAG];
    const float*  Bsb = &Bs[buf * BBUF];
#pragma unroll
    for (int ks = 0; ks < 2; ks++) {
        uint4 a[4];
#pragma unroll
        for (int mi = 0; mi < 4; mi++)
            a[mi] = Wf4[(ks * 8 + warp_m * 4 + mi) * 32 + lane];
        unsigned b0[4], b1[4];
#pragma unroll
        for (int ni = 0; ni < 4; ni++) {
            int tw = warp_n * 32 + ni * 8 + g;
            int r0 = ks * 16 + 2 * tig;
            float f0 = Bsb[(r0)     * PITCH + tw];
            float f1 = Bsb[(r0 + 1) * PITCH + tw];
            float f2 = Bsb[(r0 + 8) * PITCH + tw];
            float f3 = Bsb[(r0 + 9) * PITCH + tw];
            b0[ni] = pack_h2(f0, f1);
            b1[ni] = pack_h2(f2, f3);
        }
#pragma unroll
        for (int mi = 0; mi < 4; mi++)
#pragma unroll
            for (int ni = 0; ni < 4; ni++)
                mma16(acc[mi][ni][0], acc[mi][ni][1], acc[mi][ni][2], acc[mi][ni][3],
                      a[mi].x, a[mi].y, a[mi].z, a[mi].w, b0[ni], b1[ni]);
    }
}

// ---------------------------------------------------------------------------
// GEMM1: out[m 512][t] = W[m][k] * Xt[k][t]
// Grid (32 t, 4 mblk, 8 b) = 1024 CTAs. 3-stage cp.async, 1 sync/chunk.
// ---------------------------------------------------------------------------
__global__ __launch_bounds__(256)
void gemm1_kernel() {
    extern __shared__ float smem[];
    float* Bs = smem;
    unsigned* Wf = (unsigned*)(smem + NSTAGE * BBUF);

    int tid = threadIdx.x, lane = tid & 31, wid = tid >> 5;
    int warp_m = wid >> 2, warp_n = wid & 3;
    int g = lane >> 2, tig = lane & 3;
    int b = blockIdx.z, t0 = blockIdx.x * 128;
    int mt0 = blockIdx.y * 8;
    int m0 = blockIdx.y * 128;

    const int row = tid >> 3, cq = tid & 7;
    const int NCH = INDIM / KC;   // 4
    const uint4* wbase = (const uint4*)g_wf1h;

    auto fill1 = [&](int c) {
        const float* arow = g_xt + ((size_t)b * INDIM + c * KC + row) * TLEN + t0;
        fill_b(Bs, c % NSTAGE, arow, row, cq);
        // chunk c: K16 = 2c, 2c+1; slice src (K16, mt0): uint4 offset (K16*32+mt0)*32
        fill_w(Wf, c % NSTAGE, wbase + (size_t)((2 * c) * 32 + mt0) * 32, 32 * 32, tid);
        cp_commit();
    };

    fill1(0);
    fill1(1);

    float acc[4][4][4];
#pragma unroll
    for (int mi = 0; mi < 4; mi++)
#pragma unroll
        for (int ni = 0; ni < 4; ni++)
#pragma unroll
            for (int q = 0; q < 4; q++) acc[mi][ni][q] = 0.f;

    for (int c = 0; c < NCH; c++) {
        if (c + 2 < NCH) cp_wait1(); else cp_wait0();
        __syncthreads();
        if (c + 2 < NCH) fill1(c + 2);
        compute_chunk(Bs, Wf, c % NSTAGE, warp_m, warp_n, lane, g, tig, acc);
    }

    float* dst = (m0 < 256) ? g_bx_re : g_bx_im;
    int hbase = m0 & 255;
#pragma unroll
    for (int mi = 0; mi < 4; mi++) {
        int h = hbase + warp_m * 64 + mi * 16 + g;
#pragma unroll
        for (int ni = 0; ni < 4; ni++) {
            int t = t0 + warp_n * 32 + ni * 8 + 2 * tig;
            *(float2*)&dst[((size_t)b * HID + h) * TLEN + t] =
                make_float2(acc[mi][ni][0], acc[mi][ni][1]);
            *(float2*)&dst[((size_t)b * HID + h + 8) * TLEN + t] =
                make_float2(acc[mi][ni][2], acc[mi][ni][3]);
        }
    }
}

// ---------------------------------------------------------------------------
// Scan: inclusive complex scan over t, 8 elems/lane, prefetch distance 1
// (round-9 version), in place on g_bx, raw fp32 stores.
// ---------------------------------------------------------------------------
__global__ __launch_bounds__(256)
void scan_kernel() {
    int wg   = (blockIdx.x * blockDim.x + threadIdx.x) >> 5;
    int lane = threadIdx.x & 31;
    if (wg >= BATCH * HID) return;
    int b = wg >> 8;
    int h = wg & (HID - 1);

    float lr[8], li[8];
    lr[0] = g_lam_re[h]; li[0] = g_lam_im[h];
#pragma unroll
    for (int k = 1; k < 8; k++) {
        lr[k] = lr[k-1] * lr[0] - li[k-1] * li[0];
        li[k] = lr[k-1] * li[0] + li[k-1] * lr[0];
    }
    float pdr[5], pdi[5];
    pdr[0] = lr[7]; pdi[0] = li[7];
#pragma unroll
    for (int s = 1; s < 5; s++) {
        pdr[s] = pdr[s-1] * pdr[s-1] - pdi[s-1] * pdi[s-1];
        pdi[s] = 2.f * pdr[s-1] * pdi[s-1];
    }
    float mag = g_mag[h], th = g_th[h];
    float mp  = powf(mag, 8.f * (float)lane);
    float sa, ca;
    sincosf(th * 8.f * (float)lane, &sa, &ca);
    float c8r = mp * ca, c8i = mp * sa;

    float ccr = 0.f, cci = 0.f;
    size_t base = ((size_t)b * HID + h) * TLEN;
    const int NCH = TLEN / 256;   // 16

    size_t off = base + (size_t)lane * 8;
    float4 nr0 = *(const float4*)&g_bx_re[off];
    float4 nr1 = *(const float4*)&g_bx_re[off + 4];
    float4 ni0 = *(const float4*)&g_bx_im[off];
    float4 ni1 = *(const float4*)&g_bx_im[off + 4];

    for (int c = 0; c < NCH; c++) {
        float xr[8] = {nr0.x, nr0.y, nr0.z, nr0.w, nr1.x, nr1.y, nr1.z, nr1.w};
        float xi[8] = {ni0.x, ni0.y, ni0.z, ni0.w, ni1.x, ni1.y, ni1.z, ni1.w};
        size_t coff = off;
        if (c + 1 < NCH) {
            off += 256;
            nr0 = *(const float4*)&g_bx_re[off];
            nr1 = *(const float4*)&g_bx_re[off + 4];
            ni0 = *(const float4*)&g_bx_im[off];
            ni1 = *(const float4*)&g_bx_im[off + 4];
        }

        float yr[8], yi[8];
        yr[0] = xr[0]; yi[0] = xi[0];
#pragma unroll
        for (int k = 1; k < 8; k++) {
            yr[k] = xr[k] + lr[0] * yr[k-1] - li[0] * yi[k-1];
            yi[k] = xi[k] + lr[0] * yi[k-1] + li[0] * yr[k-1];
        }

        float sr = yr[7], si = yi[7];
#pragma unroll
        for (int s = 0; s < 5; s++) {
            int d = 1 << s;
            float tr = __shfl_up_sync(0xffffffffu, sr, d);
            float ti = __shfl_up_sync(0xffffffffu, si, d);
            if (lane >= d) {
                sr += pdr[s] * tr - pdi[s] * ti;
                si += pdr[s] * ti + pdi[s] * tr;
            }
        }
        float qr = __shfl_up_sync(0xffffffffu, sr, 1);
        float qi = __shfl_up_sync(0xffffffffu, si, 1);
        if (lane == 0) { qr = 0.f; qi = 0.f; }
        qr += c8r * ccr - c8i * cci;
        qi += c8r * cci + c8i * ccr;

        float or_[8], oi_[8];
#pragma unroll
        for (int k = 0; k < 8; k++) {
            or_[k] = yr[k] + lr[k] * qr - li[k] * qi;
            oi_[k] = yi[k] + lr[k] * qi + li[k] * qr;
        }

        ccr = __shfl_sync(0xffffffffu, or_[7], 31);
        cci = __shfl_sync(0xffffffffu, oi_[7], 31);

        *(float4*)&g_bx_re[coff]     = make_float4(or_[0], or_[1], or_[2], or_[3]);
        *(float4*)&g_bx_re[coff + 4] = make_float4(or_[4], or_[5], or_[6], or_[7]);
        *(float4*)&g_bx_im[coff]     = make_float4(oi_[0], oi_[1], oi_[2], oi_[3]);
        *(float4*)&g_bx_im[coff + 4] = make_float4(oi_[4], oi_[5], oi_[6], oi_[7]);
    }
}

// ---------------------------------------------------------------------------
// GEMM2: Y[t][o] = sum_{k<640} Wt2[o][k] * A[k][t]
// 3-stage cp.async, 1 sync/chunk. Grid (32, 8).
// ---------------------------------------------------------------------------
__global__ __launch_bounds__(256)
void gemm2_kernel(float* __restrict__ Y) {
    extern __shared__ float smemf[];
    float* Bs = smemf;
    unsigned* Wf = (unsigned*)(smemf + NSTAGE * BBUF);

    int tid = threadIdx.x, lane = tid & 31, wid = tid >> 5;
    int warp_m = wid >> 2, warp_n = wid & 3;
    int g = lane >> 2, tig = lane & 3;
    int b = blockIdx.y, t0 = blockIdx.x * 128;

    float acc[4][4][4];
#pragma unroll
    for (int mi = 0; mi < 4; mi++)
#pragma unroll
        for (int ni = 0; ni < 4; ni++)
#pragma unroll
            for (int q = 0; q < 4; q++) acc[mi][ni][q] = 0.f;

    const int row = tid >> 3, cq = tid & 7;
    const int NCH = 640 / KC;   // 20
    const uint4* wbase = (const uint4*)g_wf2h;

    auto arow_of = [&](int k) -> const float* {
        if (k < 256)      return g_bx_re + ((size_t)b * HID + k) * TLEN + t0;
        else if (k < 512) return g_bx_im + ((size_t)b * HID + (k - 256)) * TLEN + t0;
        else              return g_xt   + ((size_t)b * INDIM + (k - 512)) * TLEN + t0;
    };
    auto fill2 = [&](int c) {
        fill_b(Bs, c % NSTAGE, arow_of(c * KC + row), row, cq);
        // chunk c: K16 = 2c, 2c+1; contiguous slices of 256 uint4
        fill_w(Wf, c % NSTAGE, wbase + (size_t)c * 512, 256, tid);
        cp_commit();
    };

    fill2(0);
    fill2(1);

    for (int c = 0; c < NCH; c++) {
        if (c + 2 < NCH) cp_wait1(); else cp_wait0();
        __syncthreads();
        if (c + 2 < NCH) fill2(c + 2);
        compute_chunk(Bs, Wf, c % NSTAGE, warp_m, warp_n, lane, g, tig, acc);
    }

#pragma unroll
    for (int mi = 0; mi < 4; mi++) {
        int o = warp_m * 64 + mi * 16 + g;
#pragma unroll
        for (int ni = 0; ni < 4; ni++) {
            int t = t0 + warp_n * 32 + ni * 8 + 2 * tig;
            size_t y0 = ((size_t)b * TLEN + t) * OUTDIM;
            size_t y1 = ((size_t)b * TLEN + t + 1) * OUTDIM;
            Y[y0 + o]     = acc[mi][ni][0];
            Y[y1 + o]     = acc[mi][ni][1];
            Y[y0 + o + 8] = acc[mi][ni][2];
            Y[y1 + o + 8] = acc[mi][ni][3];
        }
    }
}

// ---------------------------------------------------------------------------
extern "C" void kernel_launch(void* const* d_in, const int* in_sizes, int n_in,
                              void* d_out, int out_size) {
    const float* X         = (const float*)d_in[0];
    const float* nu_log    = (const float*)d_in[1];
    const float* theta_log = (const float*)d_in[2];
    const float* B_re      = (const float*)d_in[3];
    const float* B_im      = (const float*)d_in[4];
    const float* C_re      = (const float*)d_in[5];
    const float* C_im      = (const float*)d_in[6];
    const float* D         = (const float*)d_in[7];
    float* Y = (float*)d_out;

    cudaFuncSetAttribute(gemm1_kernel, cudaFuncAttributeMaxDynamicSharedMemorySize, SMEM_BYTES);
    cudaFuncSetAttribute(gemm2_kernel, cudaFuncAttributeMaxDynamicSharedMemorySize, SMEM_BYTES);

    prep_all_kernel<<<NB_ALL, 256>>>(X, nu_log, theta_log, B_re, B_im, C_re, C_im, D);

    dim3 g1(TLEN / 128, 4, BATCH);
    gemm1_kernel<<<g1, 256, SMEM_BYTES>>>();

    scan_kernel<<<(BATCH * HID * 32) / 256, 256>>>();

    dim3 g2(TLEN / 128, BATCH);
    gemm2_kernel<<<g2, 256, SMEM_BYTES>>>(Y);
}

// round 12
// speedup vs baseline: 1.5953x; 1.2568x over previous
#include <cuda_runtime.h>
#include <cuda_fp16.h>
#include <cstdint>

#define BATCH 8
#define TLEN 4096
#define INDIM 128
#define OUTDIM 128
#define HID 256
#define PITCH_H 136            // halves per t-data smem row (272B)
#define KC 32                  // K-chunk (rows) = 2 k16 mma steps
#define BBUF_H (KC * PITCH_H)  // halves per stage (4352)
#define WFRAG 2048             // fp16 frag words (uint32) per stage
#define NSTAGE 3
#define SMEM_BYTES (NSTAGE * (BBUF_H * 2 + WFRAG * 4))   // 50688

// ---- scratch (device globals: allocation-free rule) ----
__device__ float g_lam_re[HID];
__device__ float g_lam_im[HID];
__device__ float g_mag[HID];
__device__ float g_th[HID];
__device__ __half g_bx_re[(size_t)BATCH * HID * TLEN];   // [b][h][t] fp16
__device__ __half g_bx_im[(size_t)BATCH * HID * TLEN];
__device__ __half g_xt[(size_t)BATCH * INDIM * TLEN];    // [b][i][t] fp16
// fp16 weight fragments, mma m16n8k16 order: [K16][mt][lane][4 words]
__device__ unsigned g_wf1h[8 * 32 * 32 * 4];             // gemm1: M=512, K=128
__device__ unsigned g_wf2h[40 * 8 * 32 * 4];             // gemm2: M=128, K=640

// ---- helpers ----
__device__ __forceinline__ unsigned pack_h2(float lo, float hi) {
    unsigned d;
    asm("cvt.rn.f16x2.f32 %0, %1, %2;" : "=r"(d) : "f"(hi), "f"(lo));
    return d;
}
__device__ __forceinline__ void mma16(float& d0, float& d1, float& d2, float& d3,
                                      unsigned a0, unsigned a1, unsigned a2, unsigned a3,
                                      unsigned b0, unsigned b1) {
    asm("mma.sync.aligned.m16n8k16.row.col.f32.f16.f16.f32 "
        "{%0,%1,%2,%3}, {%4,%5,%6,%7}, {%8,%9}, {%0,%1,%2,%3};"
        : "+f"(d0), "+f"(d1), "+f"(d2), "+f"(d3)
        : "r"(a0), "r"(a1), "r"(a2), "r"(a3), "r"(b0), "r"(b1));
}
__device__ __forceinline__ unsigned smem_u32(const void* p) {
    return (unsigned)__cvta_generic_to_shared(p);
}
__device__ __forceinline__ void cp16(unsigned s, const void* g) {
    asm volatile("cp.async.cg.shared.global [%0], [%1], 16;" :: "r"(s), "l"(g));
}
__device__ __forceinline__ void cp_commit() { asm volatile("cp.async.commit_group;"); }
__device__ __forceinline__ void cp_wait1()  { asm volatile("cp.async.wait_group 1;"); }
__device__ __forceinline__ void cp_wait0()  { asm volatile("cp.async.wait_group 0;"); }

// ---------------------------------------------------------------------------
// prep_all: X transpose (fp16 packed) + fp16 weight fragments + params
// ---------------------------------------------------------------------------
#define WF1H_N (8 * 32 * 32 * 4)    // 32768 words
#define WF2H_N (40 * 8 * 32 * 4)    // 40960 words
#define NB_XT 4096
#define NB_W  ((WF1H_N + WF2H_N) / 256)   // 288
#define NB_ALL (NB_XT + NB_W + 1)

__global__ __launch_bounds__(256)
void prep_all_kernel(const float* __restrict__ X,
                     const float* __restrict__ nu_log,
                     const float* __restrict__ theta_log,
                     const float* __restrict__ Bre, const float* __restrict__ Bim,
                     const float* __restrict__ Cre, const float* __restrict__ Cim,
                     const float* __restrict__ Dm) {
    __shared__ float tile[32][33];
    int bid = blockIdx.x;
    int tid = threadIdx.x;

    if (bid < NB_XT) {
        int t0 = (bid & 127) * 32;
        int i0 = ((bid >> 7) & 3) * 32;
        int b  = bid >> 9;
#pragma unroll
        for (int r = 0; r < 4; r++) {
            int idx = tid + 256 * r;
            int tl = idx >> 5, il = idx & 31;
            tile[tl][il] = X[((size_t)b * TLEN + t0 + tl) * INDIM + i0 + il];
        }
        __syncthreads();
        // write half2-packed over t: 512 uint32
#pragma unroll
        for (int r = 0; r < 2; r++) {
            int idx = tid + 256 * r;
            int il = idx >> 4, tp = idx & 15;
            unsigned w = pack_h2(tile[2 * tp][il], tile[2 * tp + 1][il]);
            ((unsigned*)g_xt)[(((size_t)b * INDIM + i0 + il) * TLEN + t0) / 2 + tp] = w;
        }
    } else if (bid < NB_XT + NB_W) {
        int idx = (bid - NB_XT) * 256 + tid;
        if (idx < WF1H_N) {
            int j = idx & 3, lane = (idx >> 2) & 31, mt = (idx >> 7) & 31, K16 = idx >> 12;
            int g = lane >> 2, tig = lane & 3;
            int m = mt * 16 + g + (j & 1) * 8;
            int k0 = K16 * 16 + 2 * tig + (j >> 1) * 8;
            int h = m & 255;
            float mag = expf(-expf(nu_log[h]));
            float gam = sqrtf(fmaxf(1.0f - mag * mag, 0.0f));
            const float* wrow = (m < 256) ? &Bre[(size_t)h * INDIM] : &Bim[(size_t)h * INDIM];
            g_wf1h[idx] = pack_h2(gam * wrow[k0], gam * wrow[k0 + 1]);
        } else {
            int e = idx - WF1H_N;
            int j = e & 3, lane = (e >> 2) & 31, mt = (e >> 7) & 7, K16 = e >> 10;
            int g = lane >> 2, tig = lane & 3;
            int o = mt * 16 + g + (j & 1) * 8;
            int k0 = K16 * 16 + 2 * tig + (j >> 1) * 8;
            float v0, v1;
            if (k0 < 256)      { v0 =  Cre[(size_t)o * HID + k0];         v1 =  Cre[(size_t)o * HID + k0 + 1]; }
            else if (k0 < 512) { v0 = -Cim[(size_t)o * HID + k0 - 256];   v1 = -Cim[(size_t)o * HID + k0 - 255]; }
            else               { v0 =  Dm[(size_t)o * INDIM + k0 - 512];  v1 =  Dm[(size_t)o * INDIM + k0 - 511]; }
            g_wf2h[e] = pack_h2(v0, v1);
        }
    } else {
        int h = tid;
        if (h < HID) {
            float mag = expf(-expf(nu_log[h]));
            float th  = expf(theta_log[h]);
            g_mag[h] = mag;
            g_th[h]  = th;
            g_lam_re[h] = mag * cosf(th);
            g_lam_im[h] = mag * sinf(th);
        }
    }
}

// ---------------------------------------------------------------------------
// smem fill helpers
// ---------------------------------------------------------------------------
// half rows: 128 halves = 256B = 16 cp16 per row; 512 total / 256 thr = 2 each
__device__ __forceinline__ void fill_b(__half* Bsh, int buf, const __half* arow,
                                       int row, int cq) {
    unsigned sb = smem_u32(&Bsh[buf * BBUF_H + row * PITCH_H]);
#pragma unroll
    for (int r = 0; r < 2; r++) {
        int c = cq + 8 * r;
        cp16(sb + 16 * c, arow + 8 * c);
    }
}
__device__ __forceinline__ void fill_w(unsigned* Wf, int buf, const uint4* wsrc,
                                       int slice_stride_u4, int tid) {
    unsigned sw = smem_u32(&Wf[buf * WFRAG]);
#pragma unroll
    for (int r = 0; r < 2; r++) {
        int fidx = tid + r * 256;
        int sl = fidx >> 8, rem = fidx & 255;
        cp16(sw + 16 * fidx, wsrc + sl * slice_stride_u4 + rem);
    }
}
// compute one KC=32 chunk = 2 k16 steps; A = fp16 frags, B = half rows
__device__ __forceinline__ void compute_chunk(const __half* Bsh, const unsigned* Wf,
                                              int buf, int warp_m, int warp_n,
                                              int lane, int g, int tig,
                                              float acc[4][4][4]) {
    const uint4*  Wf4 = (const uint4*)&Wf[buf * WFRAG];
    const __half* Bsb = &Bsh[buf * BBUF_H];
#pragma unroll
    for (int ks = 0; ks < 2; ks++) {
        uint4 a[4];
#pragma unroll
        for (int mi = 0; mi < 4; mi++)
            a[mi] = Wf4[(ks * 8 + warp_m * 4 + mi) * 32 + lane];
        unsigned b0[4], b1[4];
#pragma unroll
        for (int ni = 0; ni < 4; ni++) {
            int tw = warp_n * 32 + ni * 8 + g;
            int r0 = ks * 16 + 2 * tig;
            unsigned u0 = __half_as_ushort(Bsb[(r0)     * PITCH_H + tw]);
            unsigned u1 = __half_as_ushort(Bsb[(r0 + 1) * PITCH_H + tw]);
            unsigned u2 = __half_as_ushort(Bsb[(r0 + 8) * PITCH_H + tw]);
            unsigned u3 = __half_as_ushort(Bsb[(r0 + 9) * PITCH_H + tw]);
            b0[ni] = u0 | (u1 << 16);
            b1[ni] = u2 | (u3 << 16);
        }
#pragma unroll
        for (int mi = 0; mi < 4; mi++)
#pragma unroll
            for (int ni = 0; ni < 4; ni++)
                mma16(acc[mi][ni][0], acc[mi][ni][1], acc[mi][ni][2], acc[mi][ni][3],
                      a[mi].x, a[mi].y, a[mi].z, a[mi].w, b0[ni], b1[ni]);
    }
}

// ---------------------------------------------------------------------------
// GEMM1: out[m 512][t] = W[m][k] * Xt[k][t]
// Grid (32 t, 4 mblk, 8 b) = 1024 CTAs. 3-stage cp.async, 1 sync/chunk.
// ---------------------------------------------------------------------------
__global__ __launch_bounds__(256)
void gemm1_kernel() {
    extern __shared__ char smem[];
    __half* Bsh = (__half*)smem;
    unsigned* Wf = (unsigned*)(smem + NSTAGE * BBUF_H * 2);

    int tid = threadIdx.x, lane = tid & 31, wid = tid >> 5;
    int warp_m = wid >> 2, warp_n = wid & 3;
    int g = lane >> 2, tig = lane & 3;
    int b = blockIdx.z, t0 = blockIdx.x * 128;
    int mt0 = blockIdx.y * 8;
    int m0 = blockIdx.y * 128;

    const int row = tid >> 3, cq = tid & 7;
    const int NCH = INDIM / KC;   // 4
    const uint4* wbase = (const uint4*)g_wf1h;

    auto fill1 = [&](int c) {
        const __half* arow = g_xt + ((size_t)b * INDIM + c * KC + row) * TLEN + t0;
        fill_b(Bsh, c % NSTAGE, arow, row, cq);
        fill_w(Wf, c % NSTAGE, wbase + (size_t)((2 * c) * 32 + mt0) * 32, 32 * 32, tid);
        cp_commit();
    };

    fill1(0);
    fill1(1);

    float acc[4][4][4];
#pragma unroll
    for (int mi = 0; mi < 4; mi++)
#pragma unroll
        for (int ni = 0; ni < 4; ni++)
#pragma unroll
            for (int q = 0; q < 4; q++) acc[mi][ni][q] = 0.f;

    for (int c = 0; c < NCH; c++) {
        if (c + 2 < NCH) cp_wait1(); else cp_wait0();
        __syncthreads();
        if (c + 2 < NCH) fill1(c + 2);
        compute_chunk(Bsh, Wf, c % NSTAGE, warp_m, warp_n, lane, g, tig, acc);
    }

    // epilogue: half2-packed stores over t (t even: 2*tig)
    __half* dst = (m0 < 256) ? g_bx_re : g_bx_im;
    int hbase = m0 & 255;
#pragma unroll
    for (int mi = 0; mi < 4; mi++) {
        int h = hbase + warp_m * 64 + mi * 16 + g;
#pragma unroll
        for (int ni = 0; ni < 4; ni++) {
            int t = t0 + warp_n * 32 + ni * 8 + 2 * tig;
            ((unsigned*)dst)[(((size_t)b * HID + h) * TLEN + t) >> 1] =
                pack_h2(acc[mi][ni][0], acc[mi][ni][1]);
            ((unsigned*)dst)[(((size_t)b * HID + h + 8) * TLEN + t) >> 1] =
                pack_h2(acc[mi][ni][2], acc[mi][ni][3]);
        }
    }
}

// ---------------------------------------------------------------------------
// Scan: inclusive complex scan over t, 8 elems/lane, fp16 I/O, fp32 math.
// ---------------------------------------------------------------------------
__global__ __launch_bounds__(256)
void scan_kernel() {
    int wg   = (blockIdx.x * blockDim.x + threadIdx.x) >> 5;
    int lane = threadIdx.x & 31;
    if (wg >= BATCH * HID) return;
    int b = wg >> 8;
    int h = wg & (HID - 1);

    float lr[8], li[8];
    lr[0] = g_lam_re[h]; li[0] = g_lam_im[h];
#pragma unroll
    for (int k = 1; k < 8; k++) {
        lr[k] = lr[k-1] * lr[0] - li[k-1] * li[0];
        li[k] = lr[k-1] * li[0] + li[k-1] * lr[0];
    }
    float pdr[5], pdi[5];
    pdr[0] = lr[7]; pdi[0] = li[7];
#pragma unroll
    for (int s = 1; s < 5; s++) {
        pdr[s] = pdr[s-1] * pdr[s-1] - pdi[s-1] * pdi[s-1];
        pdi[s] = 2.f * pdr[s-1] * pdi[s-1];
    }
    float mag = g_mag[h], th = g_th[h];
    float mp  = powf(mag, 8.f * (float)lane);
    float sa, ca;
    sincosf(th * 8.f * (float)lane, &sa, &ca);
    float c8r = mp * ca, c8i = mp * sa;

    float ccr = 0.f, cci = 0.f;
    size_t base = ((size_t)b * HID + h) * TLEN;
    const int NCH = TLEN / 256;   // 16

    size_t off = base + (size_t)lane * 8;   // half index
    const uint4* pre = (const uint4*)&g_bx_re[off];
    const uint4* pim = (const uint4*)&g_bx_im[off];
    uint4 vr = *pre;
    uint4 vi = *pim;

    for (int c = 0; c < NCH; c++) {
        float xr[8], xi[8];
        {
            float2 f;
            f = __half22float2(*(__half2*)&vr.x); xr[0] = f.x; xr[1] = f.y;
            f = __half22float2(*(__half2*)&vr.y); xr[2] = f.x; xr[3] = f.y;
            f = __half22float2(*(__half2*)&vr.z); xr[4] = f.x; xr[5] = f.y;
            f = __half22float2(*(__half2*)&vr.w); xr[6] = f.x; xr[7] = f.y;
            f = __half22float2(*(__half2*)&vi.x); xi[0] = f.x; xi[1] = f.y;
            f = __half22float2(*(__half2*)&vi.y); xi[2] = f.x; xi[3] = f.y;
            f = __half22float2(*(__half2*)&vi.z); xi[4] = f.x; xi[5] = f.y;
            f = __half22float2(*(__half2*)&vi.w); xi[6] = f.x; xi[7] = f.y;
        }
        size_t coff = off;
        if (c + 1 < NCH) {
            off += 256;
            vr = *(const uint4*)&g_bx_re[off];
            vi = *(const uint4*)&g_bx_im[off];
        }

        float yr[8], yi[8];
        yr[0] = xr[0]; yi[0] = xi[0];
#pragma unroll
        for (int k = 1; k < 8; k++) {
            yr[k] = xr[k] + lr[0] * yr[k-1] - li[0] * yi[k-1];
            yi[k] = xi[k] + lr[0] * yi[k-1] + li[0] * yr[k-1];
        }

        float sr = yr[7], si = yi[7];
#pragma unroll
        for (int s = 0; s < 5; s++) {
            int d = 1 << s;
            float tr = __shfl_up_sync(0xffffffffu, sr, d);
            float ti = __shfl_up_sync(0xffffffffu, si, d);
            if (lane >= d) {
                sr += pdr[s] * tr - pdi[s] * ti;
                si += pdr[s] * ti + pdi[s] * tr;
            }
        }
        float qr = __shfl_up_sync(0xffffffffu, sr, 1);
        float qi = __shfl_up_sync(0xffffffffu, si, 1);
        if (lane == 0) { qr = 0.f; qi = 0.f; }
        qr += c8r * ccr - c8i * cci;
        qi += c8r * cci + c8i * ccr;

        float or_[8], oi_[8];
#pragma unroll
        for (int k = 0; k < 8; k++) {
            or_[k] = yr[k] + lr[k] * qr - li[k] * qi;
            oi_[k] = yi[k] + lr[k] * qi + li[k] * qr;
        }

        ccr = __shfl_sync(0xffffffffu, or_[7], 31);
        cci = __shfl_sync(0xffffffffu, oi_[7], 31);

        uint4 wr, wi;
        wr.x = pack_h2(or_[0], or_[1]); wr.y = pack_h2(or_[2], or_[3]);
        wr.z = pack_h2(or_[4], or_[5]); wr.w = pack_h2(or_[6], or_[7]);
        wi.x = pack_h2(oi_[0], oi_[1]); wi.y = pack_h2(oi_[2], oi_[3]);
        wi.z = pack_h2(oi_[4], oi_[5]); wi.w = pack_h2(oi_[6], oi_[7]);
        *(uint4*)&g_bx_re[coff] = wr;
        *(uint4*)&g_bx_im[coff] = wi;
    }
}

// ---------------------------------------------------------------------------
// GEMM2: Y[t][o] = sum_{k<640} Wt2[o][k] * A[k][t]
// 3-stage cp.async, 1 sync/chunk. Grid (32, 8).
// ---------------------------------------------------------------------------
__global__ __launch_bounds__(256)
void gemm2_kernel(float* __restrict__ Y) {
    extern __shared__ char smem[];
    __half* Bsh = (__half*)smem;
    unsigned* Wf = (unsigned*)(smem + NSTAGE * BBUF_H * 2);

    int tid = threadIdx.x, lane = tid & 31, wid = tid >> 5;
    int warp_m = wid >> 2, warp_n = wid & 3;
    int g = lane >> 2, tig = lane & 3;
    int b = blockIdx.y, t0 = blockIdx.x * 128;

    float acc[4][4][4];
#pragma unroll
    for (int mi = 0; mi < 4; mi++)
#pragma unroll
        for (int ni = 0; ni < 4; ni++)
#pragma unroll
            for (int q = 0; q < 4; q++) acc[mi][ni][q] = 0.f;

    const int row = tid >> 3, cq = tid & 7;
    const int NCH = 640 / KC;   // 20
    const uint4* wbase = (const uint4*)g_wf2h;

    auto arow_of = [&](int k) -> const __half* {
        if (k < 256)      return g_bx_re + ((size_t)b * HID + k) * TLEN + t0;
        else if (k < 512) return g_bx_im + ((size_t)b * HID + (k - 256)) * TLEN + t0;
        else              return g_xt   + ((size_t)b * INDIM + (k - 512)) * TLEN + t0;
    };
    auto fill2 = [&](int c) {
        fill_b(Bsh, c % NSTAGE, arow_of(c * KC + row), row, cq);
        fill_w(Wf, c % NSTAGE, wbase + (size_t)c * 512, 256, tid);
        cp_commit();
    };

    fill2(0);
    fill2(1);

    for (int c = 0; c < NCH; c++) {
        if (c + 2 < NCH) cp_wait1(); else cp_wait0();
        __syncthreads();
        if (c + 2 < NCH) fill2(c + 2);
        compute_chunk(Bsh, Wf, c % NSTAGE, warp_m, warp_n, lane, g, tig, acc);
    }

#pragma unroll
    for (int mi = 0; mi < 4; mi++) {
        int o = warp_m * 64 + mi * 16 + g;
#pragma unroll
        for (int ni = 0; ni < 4; ni++) {
            int t = t0 + warp_n * 32 + ni * 8 + 2 * tig;
            size_t y0 = ((size_t)b * TLEN + t) * OUTDIM;
            size_t y1 = ((size_t)b * TLEN + t + 1) * OUTDIM;
            Y[y0 + o]     = acc[mi][ni][0];
            Y[y1 + o]     = acc[mi][ni][1];
            Y[y0 + o + 8] = acc[mi][ni][2];
            Y[y1 + o + 8] = acc[mi][ni][3];
        }
    }
}

// ---------------------------------------------------------------------------
extern "C" void kernel_launch(void* const* d_in, const int* in_sizes, int n_in,
                              void* d_out, int out_size) {
    const float* X         = (const float*)d_in[0];
    const float* nu_log    = (const float*)d_in[1];
    const float* theta_log = (const float*)d_in[2];
    const float* B_re      = (const float*)d_in[3];
    const float* B_im      = (const float*)d_in[4];
    const float* C_re      = (const float*)d_in[5];
    const float* C_im      = (const float*)d_in[6];
    const float* D         = (const float*)d_in[7];
    float* Y = (float*)d_out;

    cudaFuncSetAttribute(gemm1_kernel, cudaFuncAttributeMaxDynamicSharedMemorySize, SMEM_BYTES);
    cudaFuncSetAttribute(gemm2_kernel, cudaFuncAttributeMaxDynamicSharedMemorySize, SMEM_BYTES);

    prep_all_kernel<<<NB_ALL, 256>>>(X, nu_log, theta_log, B_re, B_im, C_re, C_im, D);

    dim3 g1(TLEN / 128, 4, BATCH);
    gemm1_kernel<<<g1, 256, SMEM_BYTES>>>();

    scan_kernel<<<(BATCH * HID * 32) / 256, 256>>>();

    dim3 g2(TLEN / 128, BATCH);
    gemm2_kernel<<<g2, 256, SMEM_BYTES>>>(Y);
}

// round 13
// speedup vs baseline: 1.7634x; 1.1054x over previous
#include <cuda_runtime.h>
#include <cuda_fp16.h>
#include <cstdint>

#define BATCH 8
#define TLEN 4096
#define INDIM 128
#define OUTDIM 128
#define HID 256
#define PITCH_H 136            // halves per t-data smem row (272B)
#define KC 32                  // K-chunk (rows) = 2 k16 mma steps
#define BBUF_H (KC * PITCH_H)  // halves per stage (4352)
#define WFRAG 2048             // fp16 frag words (uint32) per stage
#define NSTAGE 3
#define SMEM_BYTES (NSTAGE * (BBUF_H * 2 + WFRAG * 4))   // 50688

// ---- scratch (device globals: allocation-free rule) ----
__device__ float g_lam_re[HID];
__device__ float g_lam_im[HID];
__device__ float g_mag[HID];
__device__ float g_th[HID];
__device__ __half g_bx_re[(size_t)BATCH * HID * TLEN];   // [b][h][t] fp16
__device__ __half g_bx_im[(size_t)BATCH * HID * TLEN];
__device__ __half g_xt[(size_t)BATCH * INDIM * TLEN];    // [b][i][t] fp16
// fp16 weight fragments, mma m16n8k16 order: [K16][mt][lane][4 words]
__device__ unsigned g_wf1h[8 * 32 * 32 * 4];             // gemm1: M=512, K=128
__device__ unsigned g_wf2h[40 * 8 * 32 * 4];             // gemm2: M=128, K=640

// ---- helpers ----
__device__ __forceinline__ unsigned pack_h2(float lo, float hi) {
    unsigned d;
    asm("cvt.rn.f16x2.f32 %0, %1, %2;" : "=r"(d) : "f"(hi), "f"(lo));
    return d;
}
__device__ __forceinline__ void mma16(float& d0, float& d1, float& d2, float& d3,
                                      unsigned a0, unsigned a1, unsigned a2, unsigned a3,
                                      unsigned b0, unsigned b1) {
    asm("mma.sync.aligned.m16n8k16.row.col.f32.f16.f16.f32 "
        "{%0,%1,%2,%3}, {%4,%5,%6,%7}, {%8,%9}, {%0,%1,%2,%3};"
        : "+f"(d0), "+f"(d1), "+f"(d2), "+f"(d3)
        : "r"(a0), "r"(a1), "r"(a2), "r"(a3), "r"(b0), "r"(b1));
}
__device__ __forceinline__ void ldsm4t(unsigned& r0, unsigned& r1,
                                       unsigned& r2, unsigned& r3, unsigned addr) {
    asm volatile("ldmatrix.sync.aligned.m8n8.x4.trans.shared.b16 {%0,%1,%2,%3}, [%4];"
        : "=r"(r0), "=r"(r1), "=r"(r2), "=r"(r3) : "r"(addr));
}
__device__ __forceinline__ unsigned smem_u32(const void* p) {
    return (unsigned)__cvta_generic_to_shared(p);
}
__device__ __forceinline__ void cp16(unsigned s, const void* g) {
    asm volatile("cp.async.cg.shared.global [%0], [%1], 16;" :: "r"(s), "l"(g));
}
__device__ __forceinline__ void cp_commit() { asm volatile("cp.async.commit_group;"); }
__device__ __forceinline__ void cp_wait1()  { asm volatile("cp.async.wait_group 1;"); }
__device__ __forceinline__ void cp_wait0()  { asm volatile("cp.async.wait_group 0;"); }

// ---------------------------------------------------------------------------
// prep_all: X transpose (fp16 packed) + fp16 weight fragments + params
// ---------------------------------------------------------------------------
#define WF1H_N (8 * 32 * 32 * 4)    // 32768 words
#define WF2H_N (40 * 8 * 32 * 4)    // 40960 words
#define NB_XT 4096
#define NB_W  ((WF1H_N + WF2H_N) / 256)   // 288
#define NB_ALL (NB_XT + NB_W + 1)

__global__ __launch_bounds__(256)
void prep_all_kernel(const float* __restrict__ X,
                     const float* __restrict__ nu_log,
                     const float* __restrict__ theta_log,
                     const float* __restrict__ Bre, const float* __restrict__ Bim,
                     const float* __restrict__ Cre, const float* __restrict__ Cim,
                     const float* __restrict__ Dm) {
    __shared__ float tile[32][33];
    int bid = blockIdx.x;
    int tid = threadIdx.x;

    if (bid < NB_XT) {
        int t0 = (bid & 127) * 32;
        int i0 = ((bid >> 7) & 3) * 32;
        int b  = bid >> 9;
#pragma unroll
        for (int r = 0; r < 4; r++) {
            int idx = tid + 256 * r;
            int tl = idx >> 5, il = idx & 31;
            tile[tl][il] = X[((size_t)b * TLEN + t0 + tl) * INDIM + i0 + il];
        }
        __syncthreads();
#pragma unroll
        for (int r = 0; r < 2; r++) {
            int idx = tid + 256 * r;
            int il = idx >> 4, tp = idx & 15;
            unsigned w = pack_h2(tile[2 * tp][il], tile[2 * tp + 1][il]);
            ((unsigned*)g_xt)[(((size_t)b * INDIM + i0 + il) * TLEN + t0) / 2 + tp] = w;
        }
    } else if (bid < NB_XT + NB_W) {
        int idx = (bid - NB_XT) * 256 + tid;
        if (idx < WF1H_N) {
            int j = idx & 3, lane = (idx >> 2) & 31, mt = (idx >> 7) & 31, K16 = idx >> 12;
            int g = lane >> 2, tig = lane & 3;
            int m = mt * 16 + g + (j & 1) * 8;
            int k0 = K16 * 16 + 2 * tig + (j >> 1) * 8;
            int h = m & 255;
            float mag = expf(-expf(nu_log[h]));
            float gam = sqrtf(fmaxf(1.0f - mag * mag, 0.0f));
            const float* wrow = (m < 256) ? &Bre[(size_t)h * INDIM] : &Bim[(size_t)h * INDIM];
            g_wf1h[idx] = pack_h2(gam * wrow[k0], gam * wrow[k0 + 1]);
        } else {
            int e = idx - WF1H_N;
            int j = e & 3, lane = (e >> 2) & 31, mt = (e >> 7) & 7, K16 = e >> 10;
            int g = lane >> 2, tig = lane & 3;
            int o = mt * 16 + g + (j & 1) * 8;
            int k0 = K16 * 16 + 2 * tig + (j >> 1) * 8;
            float v0, v1;
            if (k0 < 256)      { v0 =  Cre[(size_t)o * HID + k0];         v1 =  Cre[(size_t)o * HID + k0 + 1]; }
            else if (k0 < 512) { v0 = -Cim[(size_t)o * HID + k0 - 256];   v1 = -Cim[(size_t)o * HID + k0 - 255]; }
            else               { v0 =  Dm[(size_t)o * INDIM + k0 - 512];  v1 =  Dm[(size_t)o * INDIM + k0 - 511]; }
            g_wf2h[e] = pack_h2(v0, v1);
        }
    } else {
        int h = tid;
        if (h < HID) {
            float mag = expf(-expf(nu_log[h]));
            float th  = expf(theta_log[h]);
            g_mag[h] = mag;
            g_th[h]  = th;
            g_lam_re[h] = mag * cosf(th);
            g_lam_im[h] = mag * sinf(th);
        }
    }
}

// ---------------------------------------------------------------------------
// smem fill helpers
// ---------------------------------------------------------------------------
__device__ __forceinline__ void fill_b(__half* Bsh, int buf, const __half* arow,
                                       int row, int cq) {
    unsigned sb = smem_u32(&Bsh[buf * BBUF_H + row * PITCH_H]);
#pragma unroll
    for (int r = 0; r < 2; r++) {
        int c = cq + 8 * r;
        cp16(sb + 16 * c, arow + 8 * c);
    }
}
__device__ __forceinline__ void fill_w(unsigned* Wf, int buf, const uint4* wsrc,
                                       int slice_stride_u4, int tid) {
    unsigned sw = smem_u32(&Wf[buf * WFRAG]);
#pragma unroll
    for (int r = 0; r < 2; r++) {
        int fidx = tid + r * 256;
        int sl = fidx >> 8, rem = fidx & 255;
        cp16(sw + 16 * fidx, wsrc + sl * slice_stride_u4 + rem);
    }
}
// compute one KC=32 chunk = 2 k16 steps; A = fp16 frags (LDS.128),
// B = ldmatrix.x4.trans from k-major half rows (2 LDSM per k16 step).
__device__ __forceinline__ void compute_chunk(const __half* Bsh, const unsigned* Wf,
                                              int buf, int warp_m, int warp_n,
                                              int lane, float acc[4][4][4]) {
    const uint4*  Wf4 = (const uint4*)&Wf[buf * WFRAG];
    const __half* Bsb = &Bsh[buf * BBUF_H];
    // lane addressing: krow = (lane & 15), col = warp_n*32 + pair*16 + (lane>=16)*8
    unsigned baddr = smem_u32(Bsb + (lane & 15) * PITCH_H + warp_n * 32 + ((lane >> 4) << 3));
#pragma unroll
    for (int ks = 0; ks < 2; ks++) {
        uint4 a[4];
#pragma unroll
        for (int mi = 0; mi < 4; mi++)
            a[mi] = Wf4[(ks * 8 + warp_m * 4 + mi) * 32 + lane];
        unsigned b0[4], b1[4];
        unsigned ksa = baddr + ks * 16 * PITCH_H * 2;
        ldsm4t(b0[0], b1[0], b0[1], b1[1], ksa);        // n-groups 0,1
        ldsm4t(b0[2], b1[2], b0[3], b1[3], ksa + 32);   // n-groups 2,3 (+16 halves)
#pragma unroll
        for (int mi = 0; mi < 4; mi++)
#pragma unroll
            for (int ni = 0; ni < 4; ni++)
                mma16(acc[mi][ni][0], acc[mi][ni][1], acc[mi][ni][2], acc[mi][ni][3],
                      a[mi].x, a[mi].y, a[mi].z, a[mi].w, b0[ni], b1[ni]);
    }
}

// ---------------------------------------------------------------------------
// GEMM1: out[m 512][t] = W[m][k] * Xt[k][t]
// Grid (32 t, 4 mblk, 8 b) = 1024 CTAs. 3-stage cp.async, 1 sync/chunk.
// ---------------------------------------------------------------------------
__global__ __launch_bounds__(256)
void gemm1_kernel() {
    extern __shared__ char smem[];
    __half* Bsh = (__half*)smem;
    unsigned* Wf = (unsigned*)(smem + NSTAGE * BBUF_H * 2);

    int tid = threadIdx.x, lane = tid & 31, wid = tid >> 5;
    int warp_m = wid >> 2, warp_n = wid & 3;
    int g = lane >> 2, tig = lane & 3;
    int b = blockIdx.z, t0 = blockIdx.x * 128;
    int mt0 = blockIdx.y * 8;
    int m0 = blockIdx.y * 128;

    const int row = tid >> 3, cq = tid & 7;
    const int NCH = INDIM / KC;   // 4
    const uint4* wbase = (const uint4*)g_wf1h;

    auto fill1 = [&](int c) {
        const __half* arow = g_xt + ((size_t)b * INDIM + c * KC + row) * TLEN + t0;
        fill_b(Bsh, c % NSTAGE, arow, row, cq);
        fill_w(Wf, c % NSTAGE, wbase + (size_t)((2 * c) * 32 + mt0) * 32, 32 * 32, tid);
        cp_commit();
    };

    fill1(0);
    fill1(1);

    float acc[4][4][4];
#pragma unroll
    for (int mi = 0; mi < 4; mi++)
#pragma unroll
        for (int ni = 0; ni < 4; ni++)
#pragma unroll
            for (int q = 0; q < 4; q++) acc[mi][ni][q] = 0.f;

    for (int c = 0; c < NCH; c++) {
        if (c + 2 < NCH) cp_wait1(); else cp_wait0();
        __syncthreads();
        if (c + 2 < NCH) fill1(c + 2);
        compute_chunk(Bsh, Wf, c % NSTAGE, warp_m, warp_n, lane, acc);
    }

    // epilogue: half2-packed stores over t (t even: 2*tig)
    __half* dst = (m0 < 256) ? g_bx_re : g_bx_im;
    int hbase = m0 & 255;
#pragma unroll
    for (int mi = 0; mi < 4; mi++) {
        int h = hbase + warp_m * 64 + mi * 16 + g;
#pragma unroll
        for (int ni = 0; ni < 4; ni++) {
            int t = t0 + warp_n * 32 + ni * 8 + 2 * tig;
            ((unsigned*)dst)[(((size_t)b * HID + h) * TLEN + t) >> 1] =
                pack_h2(acc[mi][ni][0], acc[mi][ni][1]);
            ((unsigned*)dst)[(((size_t)b * HID + h + 8) * TLEN + t) >> 1] =
                pack_h2(acc[mi][ni][2], acc[mi][ni][3]);
        }
    }
}

// ---------------------------------------------------------------------------
// Scan: inclusive complex scan over t, 8 elems/lane, fp16 I/O, fp32 math.
// ---------------------------------------------------------------------------
__global__ __launch_bounds__(256)
void scan_kernel() {
    int wg   = (blockIdx.x * blockDim.x + threadIdx.x) >> 5;
    int lane = threadIdx.x & 31;
    if (wg >= BATCH * HID) return;
    int b = wg >> 8;
    int h = wg & (HID - 1);

    float lr[8], li[8];
    lr[0] = g_lam_re[h]; li[0] = g_lam_im[h];
#pragma unroll
    for (int k = 1; k < 8; k++) {
        lr[k] = lr[k-1] * lr[0] - li[k-1] * li[0];
        li[k] = lr[k-1] * li[0] + li[k-1] * lr[0];
    }
    float pdr[5], pdi[5];
    pdr[0] = lr[7]; pdi[0] = li[7];
#pragma unroll
    for (int s = 1; s < 5; s++) {
        pdr[s] = pdr[s-1] * pdr[s-1] - pdi[s-1] * pdi[s-1];
        pdi[s] = 2.f * pdr[s-1] * pdi[s-1];
    }
    float mag = g_mag[h], th = g_th[h];
    float mp  = powf(mag, 8.f * (float)lane);
    float sa, ca;
    sincosf(th * 8.f * (float)lane, &sa, &ca);
    float c8r = mp * ca, c8i = mp * sa;

    float ccr = 0.f, cci = 0.f;
    size_t base = ((size_t)b * HID + h) * TLEN;
    const int NCH = TLEN / 256;   // 16

    size_t off = base + (size_t)lane * 8;   // half index
    uint4 vr = *(const uint4*)&g_bx_re[off];
    uint4 vi = *(const uint4*)&g_bx_im[off];

    for (int c = 0; c < NCH; c++) {
        float xr[8], xi[8];
        {
            float2 f;
            f = __half22float2(*(__half2*)&vr.x); xr[0] = f.x; xr[1] = f.y;
            f = __half22float2(*(__half2*)&vr.y); xr[2] = f.x; xr[3] = f.y;
            f = __half22float2(*(__half2*)&vr.z); xr[4] = f.x; xr[5] = f.y;
            f = __half22float2(*(__half2*)&vr.w); xr[6] = f.x; xr[7] = f.y;
            f = __half22float2(*(__half2*)&vi.x); xi[0] = f.x; xi[1] = f.y;
            f = __half22float2(*(__half2*)&vi.y); xi[2] = f.x; xi[3] = f.y;
            f = __half22float2(*(__half2*)&vi.z); xi[4] = f.x; xi[5] = f.y;
            f = __half22float2(*(__half2*)&vi.w); xi[6] = f.x; xi[7] = f.y;
        }
        size_t coff = off;
        if (c + 1 < NCH) {
            off += 256;
            vr = *(const uint4*)&g_bx_re[off];
            vi = *(const uint4*)&g_bx_im[off];
        }

        float yr[8], yi[8];
        yr[0] = xr[0]; yi[0] = xi[0];
#pragma unroll
        for (int k = 1; k < 8; k++) {
            yr[k] = xr[k] + lr[0] * yr[k-1] - li[0] * yi[k-1];
            yi[k] = xi[k] + lr[0] * yi[k-1] + li[0] * yr[k-1];
        }

        float sr = yr[7], si = yi[7];
#pragma unroll
        for (int s = 0; s < 5; s++) {
            int d = 1 << s;
            float tr = __shfl_up_sync(0xffffffffu, sr, d);
            float ti = __shfl_up_sync(0xffffffffu, si, d);
            if (lane >= d) {
                sr += pdr[s] * tr - pdi[s] * ti;
                si += pdr[s] * ti + pdi[s] * tr;
            }
        }
        float qr = __shfl_up_sync(0xffffffffu, sr, 1);
        float qi = __shfl_up_sync(0xffffffffu, si, 1);
        if (lane == 0) { qr = 0.f; qi = 0.f; }
        qr += c8r * ccr - c8i * cci;
        qi += c8r * cci + c8i * ccr;

        float or_[8], oi_[8];
#pragma unroll
        for (int k = 0; k < 8; k++) {
            or_[k] = yr[k] + lr[k] * qr - li[k] * qi;
            oi_[k] = yi[k] + lr[k] * qi + li[k] * qr;
        }

        ccr = __shfl_sync(0xffffffffu, or_[7], 31);
        cci = __shfl_sync(0xffffffffu, oi_[7], 31);

        uint4 wr, wi;
        wr.x = pack_h2(or_[0], or_[1]); wr.y = pack_h2(or_[2], or_[3]);
        wr.z = pack_h2(or_[4], or_[5]); wr.w = pack_h2(or_[6], or_[7]);
        wi.x = pack_h2(oi_[0], oi_[1]); wi.y = pack_h2(oi_[2], oi_[3]);
        wi.z = pack_h2(oi_[4], oi_[5]); wi.w = pack_h2(oi_[6], oi_[7]);
        *(uint4*)&g_bx_re[coff] = wr;
        *(uint4*)&g_bx_im[coff] = wi;
    }
}

// ---------------------------------------------------------------------------
// GEMM2: Y[t][o] = sum_{k<640} Wt2[o][k] * A[k][t]
// 3-stage cp.async, 1 sync/chunk. Grid (32, 8).
// ---------------------------------------------------------------------------
__global__ __launch_bounds__(256)
void gemm2_kernel(float* __restrict__ Y) {
    extern __shared__ char smem[];
    __half* Bsh = (__half*)smem;
    unsigned* Wf = (unsigned*)(smem + NSTAGE * BBUF_H * 2);

    int tid = threadIdx.x, lane = tid & 31, wid = tid >> 5;
    int warp_m = wid >> 2, warp_n = wid & 3;
    int g = lane >> 2, tig = lane & 3;
    int b = blockIdx.y, t0 = blockIdx.x * 128;

    float acc[4][4][4];
#pragma unroll
    for (int mi = 0; mi < 4; mi++)
#pragma unroll
        for (int ni = 0; ni < 4; ni++)
#pragma unroll
            for (int q = 0; q < 4; q++) acc[mi][ni][q] = 0.f;

    const int row = tid >> 3, cq = tid & 7;
    const int NCH = 640 / KC;   // 20
    const uint4* wbase = (const uint4*)g_wf2h;

    auto arow_of = [&](int k) -> const __half* {
        if (k < 256)      return g_bx_re + ((size_t)b * HID + k) * TLEN + t0;
        else if (k < 512) return g_bx_im + ((size_t)b * HID + (k - 256)) * TLEN + t0;
        else              return g_xt   + ((size_t)b * INDIM + (k - 512)) * TLEN + t0;
    };
    auto fill2 = [&](int c) {
        fill_b(Bsh, c % NSTAGE, arow_of(c * KC + row), row, cq);
        fill_w(Wf, c % NSTAGE, wbase + (size_t)c * 512, 256, tid);
        cp_commit();
    };

    fill2(0);
    fill2(1);

    for (int c = 0; c < NCH; c++) {
        if (c + 2 < NCH) cp_wait1(); else cp_wait0();
        __syncthreads();
        if (c + 2 < NCH) fill2(c + 2);
        compute_chunk(Bsh, Wf, c % NSTAGE, warp_m, warp_n, lane, acc);
    }

#pragma unroll
    for (int mi = 0; mi < 4; mi++) {
        int o = warp_m * 64 + mi * 16 + g;
#pragma unroll
        for (int ni = 0; ni < 4; ni++) {
            int t = t0 + warp_n * 32 + ni * 8 + 2 * tig;
            size_t y0 = ((size_t)b * TLEN + t) * OUTDIM;
            size_t y1 = ((size_t)b * TLEN + t + 1) * OUTDIM;
            Y[y0 + o]     = acc[mi][ni][0];
            Y[y1 + o]     = acc[mi][ni][1];
            Y[y0 + o + 8] = acc[mi][ni][2];
            Y[y1 + o + 8] = acc[mi][ni][3];
        }
    }
}

// ---------------------------------------------------------------------------
extern "C" void kernel_launch(void* const* d_in, const int* in_sizes, int n_in,
                              void* d_out, int out_size) {
    const float* X         = (const float*)d_in[0];
    const float* nu_log    = (const float*)d_in[1];
    const float* theta_log = (const float*)d_in[2];
    const float* B_re      = (const float*)d_in[3];
    const float* B_im      = (const float*)d_in[4];
    const float* C_re      = (const float*)d_in[5];
    const float* C_im      = (const float*)d_in[6];
    const float* D         = (const float*)d_in[7];
    float* Y = (float*)d_out;

    cudaFuncSetAttribute(gemm1_kernel, cudaFuncAttributeMaxDynamicSharedMemorySize, SMEM_BYTES);
    cudaFuncSetAttribute(gemm2_kernel, cudaFuncAttributeMaxDynamicSharedMemorySize, SMEM_BYTES);

    prep_all_kernel<<<NB_ALL, 256>>>(X, nu_log, theta_log, B_re, B_im, C_re, C_im, D);

    dim3 g1(TLEN / 128, 4, BATCH);
    gemm1_kernel<<<g1, 256, SMEM_BYTES>>>();

    scan_kernel<<<(BATCH * HID * 32) / 256, 256>>>();

    dim3 g2(TLEN / 128, BATCH);
    gemm2_kernel<<<g2, 256, SMEM_BYTES>>>(Y);
}